// round 15
// baseline (speedup 1.0000x reference)
#include <cuda_runtime.h>
#include <cuda_bf16.h>
#include <cstdint>

typedef unsigned long long ull;

// ---------------- scratch (device globals: allocation-free) ----------------
__device__ float    g_xw[(size_t)64 * 1024 * 1536];   // 402 MB xw projections
__device__ uint32_t g_xh[(size_t)64 * 1024 * 256];    // x hi (bf16x2 pairs)
__device__ uint32_t g_xl[(size_t)64 * 1024 * 256];    // x lo
__device__ uint32_t g_wh[1536 * 256];                 // W^T hi
__device__ uint32_t g_wl[1536 * 256];                 // W^T lo
__device__ float    g_h0[64 * 512];
__device__ float    g_h1[64 * 512];
__device__ unsigned g_ctr[8 * 32];

// ---------------- helpers ----------------
__device__ __forceinline__ float sigf(float x) {
    return __fdividef(1.0f, 1.0f + __expf(-x));
}
__device__ __forceinline__ float tanh_acc(float x) {
    float ax = fabsf(x);
    float e = __expf(-2.0f * ax);
    float r = __fdividef(1.0f - e, 1.0f + e);
    return copysignf(r, x);
}
__device__ __forceinline__ uint32_t bf16pair(float even, float odd) {
    __nv_bfloat16 h0 = __float2bfloat16(even);
    __nv_bfloat16 h1 = __float2bfloat16(odd);
    return ((uint32_t)__bfloat16_as_ushort(h1) << 16) |
           (uint32_t)__bfloat16_as_ushort(h0);
}
__device__ __forceinline__ void split2(float x, float y,
                                       uint32_t& hi, uint32_t& lo) {
    __nv_bfloat16 hx = __float2bfloat16(x);
    __nv_bfloat16 hy = __float2bfloat16(y);
    hi = ((uint32_t)__bfloat16_as_ushort(hy) << 16) |
         (uint32_t)__bfloat16_as_ushort(hx);
    lo = bf16pair(x - __bfloat162float(hx), y - __bfloat162float(hy));
}

// ============================================================================
// Converters (phase 1 inputs)
// ============================================================================
__global__ void conv_x_kernel(const float* __restrict__ x,
                              uint32_t* __restrict__ xh,
                              uint32_t* __restrict__ xl) {
    size_t p = (size_t)blockIdx.x * 256 + threadIdx.x;
    float2 v = ((const float2*)x)[p];
    uint32_t hi, lo;
    split2(v.x, v.y, hi, lo);
    xh[p] = hi;
    xl[p] = lo;
}

__global__ void conv_w_kernel(const float* __restrict__ W,
                              uint32_t* __restrict__ wh,
                              uint32_t* __restrict__ wl) {
    int idx = blockIdx.x * 256 + threadIdx.x;
    int n = idx >> 8;
    int kp = idx & 255;
    float v0 = W[(size_t)(2 * kp) * 1536 + n];
    float v1 = W[(size_t)(2 * kp + 1) * 1536 + n];
    uint32_t hi, lo;
    split2(v0, v1, hi, lo);
    wh[idx] = hi;
    wl[idx] = lo;
}

// ============================================================================
// Phase 1 v2: xw = x @ W + b_in, bf16x3 tensor mma.
//   512 threads, 128x128 tile, 16 warps x (32M x 32N) microtile.
//   acc = 32 regs/thread (no spill under launch_bounds(512,1)).
//   cp.async double buffer, padded smem rows (APAD=20, conflict-free).
// ============================================================================
#define APAD 20
#define KPT 16

__device__ __forceinline__ void cpa16(uint32_t saddr, const void* g) {
    asm volatile("cp.async.cg.shared.global [%0], [%1], 16;"
                 :: "r"(saddr), "l"(g));
}
__device__ __forceinline__ void mma_bf16(float* c, const uint32_t* a,
                                         uint32_t b0, uint32_t b1) {
    asm volatile(
        "mma.sync.aligned.m16n8k16.row.col.f32.bf16.bf16.f32 "
        "{%0,%1,%2,%3}, {%4,%5,%6,%7}, {%8,%9}, {%0,%1,%2,%3};"
        : "+f"(c[0]), "+f"(c[1]), "+f"(c[2]), "+f"(c[3])
        : "r"(a[0]), "r"(a[1]), "r"(a[2]), "r"(a[3]), "r"(b0), "r"(b1));
}

__global__ void __launch_bounds__(512, 1) gemm_xw_bf16x3(
    const uint32_t* __restrict__ Ahg,   // [65536][256] pairs
    const uint32_t* __restrict__ Alg,
    const uint32_t* __restrict__ Bhg,   // [1536][256] pairs (W^T)
    const uint32_t* __restrict__ Blg,
    const float* __restrict__ bias,     // [2,1536], row 0
    float* __restrict__ C)              // [65536][1536]
{
    extern __shared__ uint32_t smw[];
    uint32_t* As = smw;                         // [buf][comp][128][APAD]
    uint32_t* Bs = smw + 2 * 2 * 128 * APAD;

    const int tid = threadIdx.x;
    const int lane = tid & 31;
    const int wid = tid >> 5;                   // 0..15
    const int wm = (wid & 3) * 32;
    const int wn = (wid >> 2) * 32;
    const int bm = blockIdx.y * 128;
    const int bn = blockIdx.x * 128;

    const uint32_t as_b = (uint32_t)__cvta_generic_to_shared(As);
    const uint32_t bs_b = (uint32_t)__cvta_generic_to_shared(Bs);

    float acc[2][4][4];
#pragma unroll
    for (int mf = 0; mf < 2; mf++)
#pragma unroll
        for (int nf = 0; nf < 4; nf++)
#pragma unroll
            for (int i = 0; i < 4; i++) acc[mf][nf][i] = 0.0f;

    // load slot: row = tid>>2 (0..127), j = tid&3; 4 cpa16/thread/kt
    const int row = tid >> 2, j = tid & 3;

    auto load_tile = [&](int kt, int buf) {
        int kw = kt * KPT;
        uint32_t ad = as_b + ((((buf * 2 + 0) * 128 + row) * APAD + j * 4) << 2);
        cpa16(ad, Ahg + (size_t)(bm + row) * 256 + kw + j * 4);
        ad = as_b + ((((buf * 2 + 1) * 128 + row) * APAD + j * 4) << 2);
        cpa16(ad, Alg + (size_t)(bm + row) * 256 + kw + j * 4);
        uint32_t bd = bs_b + ((((buf * 2 + 0) * 128 + row) * APAD + j * 4) << 2);
        cpa16(bd, Bhg + (size_t)(bn + row) * 256 + kw + j * 4);
        bd = bs_b + ((((buf * 2 + 1) * 128 + row) * APAD + j * 4) << 2);
        cpa16(bd, Blg + (size_t)(bn + row) * 256 + kw + j * 4);
    };

    load_tile(0, 0);
    asm volatile("cp.async.commit_group;");

    for (int kt = 0; kt < 16; kt++) {
        __syncthreads();
        if (kt < 15) load_tile(kt + 1, (kt + 1) & 1);
        asm volatile("cp.async.commit_group;");
        asm volatile("cp.async.wait_group 1;");
        __syncthreads();

        const int buf = kt & 1;
        const uint32_t* A0 = As + (buf * 2 + 0) * 128 * APAD;
        const uint32_t* A1 = As + (buf * 2 + 1) * 128 * APAD;
        const uint32_t* B0 = Bs + (buf * 2 + 0) * 128 * APAD;
        const uint32_t* B1 = Bs + (buf * 2 + 1) * 128 * APAD;

#pragma unroll
        for (int s = 0; s < 2; s++) {
            const int kb = s * 8 + (lane & 3);
            uint32_t ah[2][4], al[2][4];
#pragma unroll
            for (int mf = 0; mf < 2; mf++) {
                int r = wm + mf * 16 + (lane >> 2);
                ah[mf][0] = A0[r * APAD + kb];
                ah[mf][1] = A0[(r + 8) * APAD + kb];
                ah[mf][2] = A0[r * APAD + kb + 4];
                ah[mf][3] = A0[(r + 8) * APAD + kb + 4];
                al[mf][0] = A1[r * APAD + kb];
                al[mf][1] = A1[(r + 8) * APAD + kb];
                al[mf][2] = A1[r * APAD + kb + 4];
                al[mf][3] = A1[(r + 8) * APAD + kb + 4];
            }
#pragma unroll
            for (int nf = 0; nf < 4; nf++) {
                int n = wn + nf * 8 + (lane >> 2);
                uint32_t bh0 = B0[n * APAD + kb];
                uint32_t bh1 = B0[n * APAD + kb + 4];
                uint32_t bl0 = B1[n * APAD + kb];
                uint32_t bl1 = B1[n * APAD + kb + 4];
#pragma unroll
                for (int mf = 0; mf < 2; mf++) {
                    mma_bf16(acc[mf][nf], ah[mf], bh0, bh1);   // hi*hi
                    mma_bf16(acc[mf][nf], al[mf], bh0, bh1);   // lo*hi
                    mma_bf16(acc[mf][nf], ah[mf], bl0, bl1);   // hi*lo
                }
            }
        }
    }

    // epilogue: + bias, store
#pragma unroll
    for (int nf = 0; nf < 4; nf++) {
        int n = bn + wn + nf * 8 + 2 * (lane & 3);
        float2 bv = *(const float2*)(bias + n);
#pragma unroll
        for (int mf = 0; mf < 2; mf++) {
            int m = bm + wm + mf * 16 + (lane >> 2);
            float2 o0 = {acc[mf][nf][0] + bv.x, acc[mf][nf][1] + bv.y};
            float2 o1 = {acc[mf][nf][2] + bv.x, acc[mf][nf][3] + bv.y};
            *(float2*)(C + (size_t)m * 1536 + n) = o0;
            *(float2*)(C + (size_t)(m + 8) * 1536 + n) = o1;
        }
    }
}

// ============================================================================
// Phase 2 v7 (best): 256 CTAs = 8 bg x 32 ug, 2/SM. A = R^T, B = h.
//   Warp-local staging + per-gate-warp early release (counter = 128*t).
// ============================================================================
#define V7_NB 256
// dynamic smem layout (uint32 words)
#define V7_RLO 0        // 12288
#define V7_HHI 12288    // 2080  (8 x 260)
#define V7_HLO 14368    // 2080
#define V7_RED 16448    // 3200 floats (128 x 25)
#define V7_SB  19648    // 48
#define V7_U32 19696
#define V7_BYTES (V7_U32 * 4)

__global__ void __launch_bounds__(256, 2) gru_seq_v7(
    const float* __restrict__ xw,    // [65536, 1536]
    const float* __restrict__ rk,    // [512, 1536]
    const float* __restrict__ bias,  // [2, 1536] (row 1 = b_rec)
    float* __restrict__ out,         // [64, 1024, 512]
    float* __restrict__ h0buf,
    float* __restrict__ h1buf,
    unsigned* __restrict__ ctr)
{
    extern __shared__ uint32_t smv[];
    uint32_t* Rlo = smv + V7_RLO;
    uint32_t* hhi = smv + V7_HHI;
    uint32_t* hlo = smv + V7_HLO;
    float*    red = (float*)(smv + V7_RED);
    float*    sb  = (float*)(smv + V7_SB);

    const int tid = threadIdx.x;
    const int bgid = blockIdx.x >> 5;    // 0..7
    const int ugid = blockIdx.x & 31;    // 0..31
    const int u0 = ugid * 16;
    const int b0 = bgid * 8;

    const int w = tid >> 5;              // warp: k-chunk [64w, 64w+64)
    const int lane = tid & 31;

    // ---- preload R^T A-fragments: hi to 48 regs, lo to smem ----
    uint32_t Ah[48];
#pragma unroll
    for (int kt = 0; kt < 4; kt++)
#pragma unroll
        for (int g = 0; g < 3; g++) {
            int pb = (w * 4 + kt) * 8 + (lane & 3);
            int urow = u0 + (lane >> 2);
#pragma unroll
            for (int rr = 0; rr < 4; rr++) {
                int un = urow + ((rr & 1) ? 8 : 0);
                int kp = pb + ((rr & 2) ? 4 : 0);
                const float* q = rk + (size_t)(2 * kp) * 1536 + g * 512 + un;
                float v0 = q[0], v1 = q[1536];
                uint32_t hi, lo;
                split2(v0, v1, hi, lo);
                Ah[(kt * 3 + g) * 4 + rr] = hi;
                Rlo[((((w * 4 + kt) * 3 + g) * 4 + rr)) * 32 + lane] = lo;
            }
        }
    if (tid < 48) {
        int u = tid / 3, g = tid - u * 3;
        sb[u * 3 + g] = bias[1536 + g * 512 + u0 + u];
    }
    __syncthreads();

    // epilogue role (tid < 128): batch eb, unit eu
    const int eb = tid >> 4;
    const int eu = tid & 15;
    const float* xwp = xw + (size_t)(b0 + eb) * 1024 * 1536 + u0 + eu;
    float* outp = out + (size_t)(b0 + eb) * 524288 + u0 + eu;
    unsigned* myctr = ctr + bgid * 32;

    float hn_prev = 0.0f;

    for (int t = 0; t < 1024; t++) {
        // prefetch gate inputs (independent of h)
        float xz = 0.f, xr = 0.f, xh = 0.f;
        if (tid < 128) {
            const float* xr_ = xwp + (size_t)t * 1536;
            xz = __ldg(xr_);
            xr = __ldg(xr_ + 512);
            xh = __ldg(xr_ + 1024);
        }

        if (t > 0) {
            if (tid == 0) {
                unsigned target = (unsigned)(128 * t);   // 32 CTAs x 4 warps
                unsigned v;
                do {
                    asm volatile("ld.acquire.gpu.global.u32 %0, [%1];"
                                 : "=r"(v) : "l"(myctr) : "memory");
                } while (v < target);
            }
            __syncthreads();
        }

        // ---- warp-local staging: warp w stages k [64w,64w+64) for 8 b ----
        const float* hin = (t & 1) ? h1buf : h0buf;
#pragma unroll
        for (int i = 0; i < 4; i++) {
            int s = lane + i * 32;            // 0..127
            int b = s >> 4;                   // batch 0..7
            int f4 = s & 15;                  // float4 idx in warp's slice
            float4 v = __ldcg((const float4*)(hin + (size_t)(b0 + b) * 512 + w * 64) + f4);
            uint32_t h01, l01, h23, l23;
            split2(v.x, v.y, h01, l01);
            split2(v.z, v.w, h23, l23);
            int a = b * 260 + w * 32 + 2 * f4;
            hhi[a] = h01; hhi[a + 1] = h23;
            hlo[a] = l01; hlo[a + 1] = l23;
        }
        __syncwarp();

        // ---- tensor GEMM: A = R^T (units on M), B = h (batches on N) ----
        float accg[3][4];
#pragma unroll
        for (int g = 0; g < 3; g++)
#pragma unroll
            for (int i = 0; i < 4; i++) accg[g][i] = 0.0f;

#pragma unroll
        for (int kt = 0; kt < 4; kt++) {
            int pb = (w * 4 + kt) * 8 + (lane & 3);
            int bo = (lane >> 2) * 260;            // batch = lane>>2
            uint32_t b0h = hhi[bo + pb], b1h = hhi[bo + pb + 4];
            uint32_t b0l = hlo[bo + pb], b1l = hlo[bo + pb + 4];
#pragma unroll
            for (int g = 0; g < 3; g++) {
                const uint32_t* A = Ah + (kt * 3 + g) * 4;
                mma_bf16(accg[g], A, b0h, b1h);     // R_hi * h_hi
                mma_bf16(accg[g], A, b0l, b1l);     // R_hi * h_lo
                uint32_t al[4];
#pragma unroll
                for (int rr = 0; rr < 4; rr++)
                    al[rr] = Rlo[((((w * 4 + kt) * 3 + g) * 4 + rr)) * 32 + lane];
                mma_bf16(accg[g], al, b0h, b1h);    // R_lo * h_hi
            }
        }

        // ---- write partials: c -> D[unit row][batch col] ----
        {
            int row = lane >> 2;              // unit (low 8)
            int col = 2 * (lane & 3);         // batch
#pragma unroll
            for (int g = 0; g < 3; g++) {
                red[((col    ) * 16 + row    ) * 25 + w * 3 + g] = accg[g][0];
                red[((col + 1) * 16 + row    ) * 25 + w * 3 + g] = accg[g][1];
                red[((col    ) * 16 + row + 8) * 25 + w * 3 + g] = accg[g][2];
                red[((col + 1) * 16 + row + 8) * 25 + w * 3 + g] = accg[g][3];
            }
        }
        __syncthreads();   // red visible to gate warps

        // ---- gates + per-warp early release: gate warps 0-3 only ----
        if (tid < 128) {
            float rz = sb[eu * 3 + 0];
            float rr = sb[eu * 3 + 1];
            float rh = sb[eu * 3 + 2];
            const float* rb = red + (eb * 16 + eu) * 25;
#pragma unroll
            for (int s = 0; s < 8; s++) {
                rz += rb[s * 3 + 0];
                rr += rb[s * 3 + 1];
                rh += rb[s * 3 + 2];
            }
            float z  = sigf(xz + rz);
            float r  = sigf(xr + rr);
            float hh = tanh_acc(xh + r * rh);
            float hn = z * hn_prev + (1.0f - z) * hh;
            hn_prev = hn;
            float* hout = (t & 1) ? h0buf : h1buf;
            __stcg(hout + (b0 + eb) * 512 + u0 + eu, hn);
            __syncwarp();
            if (lane == 0) {
                asm volatile("red.release.gpu.global.add.u32 [%0], %1;"
                             :: "l"(myctr), "r"(1u) : "memory");
            }
            outp[(size_t)t * 512] = hn;
        }
    }
}

// ============================================================================
extern "C" void kernel_launch(void* const* d_in, const int* in_sizes, int n_in,
                              void* d_out, int out_size) {
    const float* x    = (const float*)d_in[0];
    const float* W    = (const float*)d_in[1];
    const float* R    = (const float*)d_in[2];
    const float* bias = (const float*)d_in[3];
    float* out = (float*)d_out;

    float *xw_ptr, *h0_ptr, *h1_ptr;
    uint32_t *xh_ptr, *xl_ptr, *wh_ptr, *wl_ptr;
    unsigned* ctr_ptr;
    cudaGetSymbolAddress((void**)&xw_ptr, g_xw);
    cudaGetSymbolAddress((void**)&xh_ptr, g_xh);
    cudaGetSymbolAddress((void**)&xl_ptr, g_xl);
    cudaGetSymbolAddress((void**)&wh_ptr, g_wh);
    cudaGetSymbolAddress((void**)&wl_ptr, g_wl);
    cudaGetSymbolAddress((void**)&h0_ptr, g_h0);
    cudaGetSymbolAddress((void**)&h1_ptr, g_h1);
    cudaGetSymbolAddress((void**)&ctr_ptr, g_ctr);

    cudaMemsetAsync(h0_ptr, 0, 64 * 512 * sizeof(float));
    cudaMemsetAsync(ctr_ptr, 0, 8 * 32 * sizeof(unsigned));

    // ---- phase 1: convert + bf16x3 tensor GEMM (512-thread, no-spill) ----
    conv_x_kernel<<<65536, 256>>>(x, xh_ptr, xl_ptr);
    conv_w_kernel<<<1536, 256>>>(W, wh_ptr, wl_ptr);

    const int smw_bytes = 2 * 2 * 2 * 128 * APAD * 4;   // 81920
    cudaFuncSetAttribute(gemm_xw_bf16x3,
                         cudaFuncAttributeMaxDynamicSharedMemorySize, smw_bytes);
    dim3 g1(12, 512);
    gemm_xw_bf16x3<<<g1, 512, smw_bytes>>>(xh_ptr, xl_ptr, wh_ptr, wl_ptr,
                                           bias, xw_ptr);

    // ---- phase 2: v7 tensor recurrence ----
    cudaFuncSetAttribute(gru_seq_v7,
                         cudaFuncAttributeMaxDynamicSharedMemorySize, V7_BYTES);
    gru_seq_v7<<<V7_NB, 256, V7_BYTES>>>(xw_ptr, R, bias, out,
                                         h0_ptr, h1_ptr, ctr_ptr);
}

// round 16
// speedup vs baseline: 1.0129x; 1.0129x over previous
#include <cuda_runtime.h>
#include <cuda_bf16.h>
#include <cstdint>

typedef unsigned long long ull;

// ---------------- scratch (device globals: allocation-free) ----------------
__device__ float    g_xw[(size_t)64 * 1024 * 1536];   // 402 MB xw projections
__device__ uint32_t g_xh[(size_t)64 * 1024 * 256];    // x hi (bf16x2 pairs)
__device__ uint32_t g_xl[(size_t)64 * 1024 * 256];    // x lo
__device__ uint32_t g_wh[1536 * 256];                 // W^T hi
__device__ uint32_t g_wl[1536 * 256];                 // W^T lo
__device__ float    g_h0[64 * 512];
__device__ float    g_h1[64 * 512];
__device__ unsigned g_ctr[8 * 32];

// ---------------- helpers ----------------
__device__ __forceinline__ float sigf(float x) {
    return __fdividef(1.0f, 1.0f + __expf(-x));
}
__device__ __forceinline__ float tanh_acc(float x) {
    float ax = fabsf(x);
    float e = __expf(-2.0f * ax);
    float r = __fdividef(1.0f - e, 1.0f + e);
    return copysignf(r, x);
}
__device__ __forceinline__ uint32_t bf16pair(float even, float odd) {
    __nv_bfloat16 h0 = __float2bfloat16(even);
    __nv_bfloat16 h1 = __float2bfloat16(odd);
    return ((uint32_t)__bfloat16_as_ushort(h1) << 16) |
           (uint32_t)__bfloat16_as_ushort(h0);
}
__device__ __forceinline__ void split2(float x, float y,
                                       uint32_t& hi, uint32_t& lo) {
    __nv_bfloat16 hx = __float2bfloat16(x);
    __nv_bfloat16 hy = __float2bfloat16(y);
    hi = ((uint32_t)__bfloat16_as_ushort(hy) << 16) |
         (uint32_t)__bfloat16_as_ushort(hx);
    lo = bf16pair(x - __bfloat162float(hx), y - __bfloat162float(hy));
}

// ============================================================================
// Converters (phase 1 inputs)
// ============================================================================
__global__ void conv_x_kernel(const float* __restrict__ x,
                              uint32_t* __restrict__ xh,
                              uint32_t* __restrict__ xl) {
    size_t p = (size_t)blockIdx.x * 256 + threadIdx.x;
    float2 v = ((const float2*)x)[p];
    uint32_t hi, lo;
    split2(v.x, v.y, hi, lo);
    xh[p] = hi;
    xl[p] = lo;
}

__global__ void conv_w_kernel(const float* __restrict__ W,
                              uint32_t* __restrict__ wh,
                              uint32_t* __restrict__ wl) {
    int idx = blockIdx.x * 256 + threadIdx.x;
    int n = idx >> 8;
    int kp = idx & 255;
    float v0 = W[(size_t)(2 * kp) * 1536 + n];
    float v1 = W[(size_t)(2 * kp + 1) * 1536 + n];
    uint32_t hi, lo;
    split2(v0, v1, hi, lo);
    wh[idx] = hi;
    wl[idx] = lo;
}

// ============================================================================
// Phase 1 v3: xw = x @ W + b_in, bf16x3 tensor mma + LDMATRIX fragment loads.
//   512 threads, 128x128 tile, 16 warps x (32M x 32N).
//   ldmatrix.m8n8.x4: A frags (per mf, s, comp), B frags (per nf, comp,
//   both s halves at once). 16 LDSM/warp/kt vs 96 LDS32 before.
// ============================================================================
#define APAD 20
#define KPT 16

__device__ __forceinline__ void cpa16(uint32_t saddr, const void* g) {
    asm volatile("cp.async.cg.shared.global [%0], [%1], 16;"
                 :: "r"(saddr), "l"(g));
}
__device__ __forceinline__ void mma_bf16(float* c, const uint32_t* a,
                                         uint32_t b0, uint32_t b1) {
    asm volatile(
        "mma.sync.aligned.m16n8k16.row.col.f32.bf16.bf16.f32 "
        "{%0,%1,%2,%3}, {%4,%5,%6,%7}, {%8,%9}, {%0,%1,%2,%3};"
        : "+f"(c[0]), "+f"(c[1]), "+f"(c[2]), "+f"(c[3])
        : "r"(a[0]), "r"(a[1]), "r"(a[2]), "r"(a[3]), "r"(b0), "r"(b1));
}
__device__ __forceinline__ void ldsm4(uint32_t* r, uint32_t addr) {
    asm volatile(
        "ldmatrix.sync.aligned.m8n8.x4.shared.b16 {%0,%1,%2,%3}, [%4];"
        : "=r"(r[0]), "=r"(r[1]), "=r"(r[2]), "=r"(r[3]) : "r"(addr));
}

__global__ void __launch_bounds__(512, 1) gemm_xw_bf16x3(
    const uint32_t* __restrict__ Ahg,   // [65536][256] pairs
    const uint32_t* __restrict__ Alg,
    const uint32_t* __restrict__ Bhg,   // [1536][256] pairs (W^T)
    const uint32_t* __restrict__ Blg,
    const float* __restrict__ bias,     // [2,1536], row 0
    float* __restrict__ C)              // [65536][1536]
{
    extern __shared__ uint32_t smw[];
    uint32_t* As = smw;                         // [buf][comp][128][APAD]
    uint32_t* Bs = smw + 2 * 2 * 128 * APAD;

    const int tid = threadIdx.x;
    const int lane = tid & 31;
    const int wid = tid >> 5;                   // 0..15
    const int wm = (wid & 3) * 32;
    const int wn = (wid >> 2) * 32;
    const int bm = blockIdx.y * 128;
    const int bn = blockIdx.x * 128;

    const uint32_t as_b = (uint32_t)__cvta_generic_to_shared(As);
    const uint32_t bs_b = (uint32_t)__cvta_generic_to_shared(Bs);

    // per-lane ldmatrix row offsets (bytes), within a comp plane
    // A x4 (per mf,s): rows wm+mf*16+(lane&15), col (lane>>4)*16 + s*32
    const uint32_t arow = (uint32_t)(wm + (lane & 15)) * (APAD * 4)
                        + (uint32_t)(lane >> 4) * 16;
    // B x4 (per nf): rows wn+nf*8+(lane&7), col (lane>>3)*16 (covers both s)
    const uint32_t brow = (uint32_t)(wn + (lane & 7)) * (APAD * 4)
                        + (uint32_t)(lane >> 3) * 16;

    float acc[2][4][4];
#pragma unroll
    for (int mf = 0; mf < 2; mf++)
#pragma unroll
        for (int nf = 0; nf < 4; nf++)
#pragma unroll
            for (int i = 0; i < 4; i++) acc[mf][nf][i] = 0.0f;

    // load slot: row = tid>>2 (0..127), j = tid&3; 4 cpa16/thread/kt
    const int row = tid >> 2, j = tid & 3;

    auto load_tile = [&](int kt, int buf) {
        int kw = kt * KPT;
        uint32_t ad = as_b + ((((buf * 2 + 0) * 128 + row) * APAD + j * 4) << 2);
        cpa16(ad, Ahg + (size_t)(bm + row) * 256 + kw + j * 4);
        ad = as_b + ((((buf * 2 + 1) * 128 + row) * APAD + j * 4) << 2);
        cpa16(ad, Alg + (size_t)(bm + row) * 256 + kw + j * 4);
        uint32_t bd = bs_b + ((((buf * 2 + 0) * 128 + row) * APAD + j * 4) << 2);
        cpa16(bd, Bhg + (size_t)(bn + row) * 256 + kw + j * 4);
        bd = bs_b + ((((buf * 2 + 1) * 128 + row) * APAD + j * 4) << 2);
        cpa16(bd, Blg + (size_t)(bn + row) * 256 + kw + j * 4);
    };

    load_tile(0, 0);
    asm volatile("cp.async.commit_group;");

    for (int kt = 0; kt < 16; kt++) {
        __syncthreads();
        if (kt < 15) load_tile(kt + 1, (kt + 1) & 1);
        asm volatile("cp.async.commit_group;");
        asm volatile("cp.async.wait_group 1;");
        __syncthreads();

        const int buf = kt & 1;
        const uint32_t off0 = (uint32_t)((buf * 2 + 0) * 128 * APAD) * 4;
        const uint32_t off1 = (uint32_t)((buf * 2 + 1) * 128 * APAD) * 4;

        // ---- B fragments: one x4 per (nf, comp), both s halves ----
        uint32_t BH[4][4], BL[4][4];
#pragma unroll
        for (int nf = 0; nf < 4; nf++) {
            uint32_t ba = bs_b + brow + (uint32_t)(nf * 8) * (APAD * 4);
            ldsm4(BH[nf], ba + off0);
            ldsm4(BL[nf], ba + off1);
        }

#pragma unroll
        for (int s = 0; s < 2; s++) {
            // ---- A fragments: one x4 per (mf, comp) for this s ----
            uint32_t AH[2][4], AL[2][4];
#pragma unroll
            for (int mf = 0; mf < 2; mf++) {
                uint32_t aa = as_b + arow + (uint32_t)(mf * 16) * (APAD * 4)
                            + (uint32_t)(s * 32);
                ldsm4(AH[mf], aa + off0);
                ldsm4(AL[mf], aa + off1);
            }
#pragma unroll
            for (int nf = 0; nf < 4; nf++) {
                uint32_t bh0 = BH[nf][s * 2], bh1 = BH[nf][s * 2 + 1];
                uint32_t bl0 = BL[nf][s * 2], bl1 = BL[nf][s * 2 + 1];
#pragma unroll
                for (int mf = 0; mf < 2; mf++) {
                    mma_bf16(acc[mf][nf], AH[mf], bh0, bh1);   // hi*hi
                    mma_bf16(acc[mf][nf], AL[mf], bh0, bh1);   // lo*hi
                    mma_bf16(acc[mf][nf], AH[mf], bl0, bl1);   // hi*lo
                }
            }
        }
    }

    // epilogue: + bias, store
#pragma unroll
    for (int nf = 0; nf < 4; nf++) {
        int n = bn + wn + nf * 8 + 2 * (lane & 3);
        float2 bv = *(const float2*)(bias + n);
#pragma unroll
        for (int mf = 0; mf < 2; mf++) {
            int m = bm + wm + mf * 16 + (lane >> 2);
            float2 o0 = {acc[mf][nf][0] + bv.x, acc[mf][nf][1] + bv.y};
            float2 o1 = {acc[mf][nf][2] + bv.x, acc[mf][nf][3] + bv.y};
            *(float2*)(C + (size_t)m * 1536 + n) = o0;
            *(float2*)(C + (size_t)(m + 8) * 1536 + n) = o1;
        }
    }
}

// ============================================================================
// Phase 2 v7 (best): 256 CTAs = 8 bg x 32 ug, 2/SM. A = R^T, B = h.
//   Warp-local staging + per-gate-warp early release (counter = 128*t).
// ============================================================================
#define V7_NB 256
// dynamic smem layout (uint32 words)
#define V7_RLO 0        // 12288
#define V7_HHI 12288    // 2080  (8 x 260)
#define V7_HLO 14368    // 2080
#define V7_RED 16448    // 3200 floats (128 x 25)
#define V7_SB  19648    // 48
#define V7_U32 19696
#define V7_BYTES (V7_U32 * 4)

__global__ void __launch_bounds__(256, 2) gru_seq_v7(
    const float* __restrict__ xw,    // [65536, 1536]
    const float* __restrict__ rk,    // [512, 1536]
    const float* __restrict__ bias,  // [2, 1536] (row 1 = b_rec)
    float* __restrict__ out,         // [64, 1024, 512]
    float* __restrict__ h0buf,
    float* __restrict__ h1buf,
    unsigned* __restrict__ ctr)
{
    extern __shared__ uint32_t smv[];
    uint32_t* Rlo = smv + V7_RLO;
    uint32_t* hhi = smv + V7_HHI;
    uint32_t* hlo = smv + V7_HLO;
    float*    red = (float*)(smv + V7_RED);
    float*    sb  = (float*)(smv + V7_SB);

    const int tid = threadIdx.x;
    const int bgid = blockIdx.x >> 5;    // 0..7
    const int ugid = blockIdx.x & 31;    // 0..31
    const int u0 = ugid * 16;
    const int b0 = bgid * 8;

    const int w = tid >> 5;              // warp: k-chunk [64w, 64w+64)
    const int lane = tid & 31;

    // ---- preload R^T A-fragments: hi to 48 regs, lo to smem ----
    uint32_t Ah[48];
#pragma unroll
    for (int kt = 0; kt < 4; kt++)
#pragma unroll
        for (int g = 0; g < 3; g++) {
            int pb = (w * 4 + kt) * 8 + (lane & 3);
            int urow = u0 + (lane >> 2);
#pragma unroll
            for (int rr = 0; rr < 4; rr++) {
                int un = urow + ((rr & 1) ? 8 : 0);
                int kp = pb + ((rr & 2) ? 4 : 0);
                const float* q = rk + (size_t)(2 * kp) * 1536 + g * 512 + un;
                float v0 = q[0], v1 = q[1536];
                uint32_t hi, lo;
                split2(v0, v1, hi, lo);
                Ah[(kt * 3 + g) * 4 + rr] = hi;
                Rlo[((((w * 4 + kt) * 3 + g) * 4 + rr)) * 32 + lane] = lo;
            }
        }
    if (tid < 48) {
        int u = tid / 3, g = tid - u * 3;
        sb[u * 3 + g] = bias[1536 + g * 512 + u0 + u];
    }
    __syncthreads();

    // epilogue role (tid < 128): batch eb, unit eu
    const int eb = tid >> 4;
    const int eu = tid & 15;
    const float* xwp = xw + (size_t)(b0 + eb) * 1024 * 1536 + u0 + eu;
    float* outp = out + (size_t)(b0 + eb) * 524288 + u0 + eu;
    unsigned* myctr = ctr + bgid * 32;

    float hn_prev = 0.0f;

    for (int t = 0; t < 1024; t++) {
        // prefetch gate inputs (independent of h)
        float xz = 0.f, xr = 0.f, xh = 0.f;
        if (tid < 128) {
            const float* xr_ = xwp + (size_t)t * 1536;
            xz = __ldg(xr_);
            xr = __ldg(xr_ + 512);
            xh = __ldg(xr_ + 1024);
        }

        if (t > 0) {
            if (tid == 0) {
                unsigned target = (unsigned)(128 * t);   // 32 CTAs x 4 warps
                unsigned v;
                do {
                    asm volatile("ld.acquire.gpu.global.u32 %0, [%1];"
                                 : "=r"(v) : "l"(myctr) : "memory");
                } while (v < target);
            }
            __syncthreads();
        }

        // ---- warp-local staging: warp w stages k [64w,64w+64) for 8 b ----
        const float* hin = (t & 1) ? h1buf : h0buf;
#pragma unroll
        for (int i = 0; i < 4; i++) {
            int s = lane + i * 32;            // 0..127
            int b = s >> 4;                   // batch 0..7
            int f4 = s & 15;                  // float4 idx in warp's slice
            float4 v = __ldcg((const float4*)(hin + (size_t)(b0 + b) * 512 + w * 64) + f4);
            uint32_t h01, l01, h23, l23;
            split2(v.x, v.y, h01, l01);
            split2(v.z, v.w, h23, l23);
            int a = b * 260 + w * 32 + 2 * f4;
            hhi[a] = h01; hhi[a + 1] = h23;
            hlo[a] = l01; hlo[a + 1] = l23;
        }
        __syncwarp();

        // ---- tensor GEMM: A = R^T (units on M), B = h (batches on N) ----
        float accg[3][4];
#pragma unroll
        for (int g = 0; g < 3; g++)
#pragma unroll
            for (int i = 0; i < 4; i++) accg[g][i] = 0.0f;

#pragma unroll
        for (int kt = 0; kt < 4; kt++) {
            int pb = (w * 4 + kt) * 8 + (lane & 3);
            int bo = (lane >> 2) * 260;            // batch = lane>>2
            uint32_t b0h = hhi[bo + pb], b1h = hhi[bo + pb + 4];
            uint32_t b0l = hlo[bo + pb], b1l = hlo[bo + pb + 4];
#pragma unroll
            for (int g = 0; g < 3; g++) {
                const uint32_t* A = Ah + (kt * 3 + g) * 4;
                mma_bf16(accg[g], A, b0h, b1h);     // R_hi * h_hi
                mma_bf16(accg[g], A, b0l, b1l);     // R_hi * h_lo
                uint32_t al[4];
#pragma unroll
                for (int rr = 0; rr < 4; rr++)
                    al[rr] = Rlo[((((w * 4 + kt) * 3 + g) * 4 + rr)) * 32 + lane];
                mma_bf16(accg[g], al, b0h, b1h);    // R_lo * h_hi
            }
        }

        // ---- write partials: c -> D[unit row][batch col] ----
        {
            int row = lane >> 2;              // unit (low 8)
            int col = 2 * (lane & 3);         // batch
#pragma unroll
            for (int g = 0; g < 3; g++) {
                red[((col    ) * 16 + row    ) * 25 + w * 3 + g] = accg[g][0];
                red[((col + 1) * 16 + row    ) * 25 + w * 3 + g] = accg[g][1];
                red[((col    ) * 16 + row + 8) * 25 + w * 3 + g] = accg[g][2];
                red[((col + 1) * 16 + row + 8) * 25 + w * 3 + g] = accg[g][3];
            }
        }
        __syncthreads();   // red visible to gate warps

        // ---- gates + per-warp early release: gate warps 0-3 only ----
        if (tid < 128) {
            float rz = sb[eu * 3 + 0];
            float rr = sb[eu * 3 + 1];
            float rh = sb[eu * 3 + 2];
            const float* rb = red + (eb * 16 + eu) * 25;
#pragma unroll
            for (int s = 0; s < 8; s++) {
                rz += rb[s * 3 + 0];
                rr += rb[s * 3 + 1];
                rh += rb[s * 3 + 2];
            }
            float z  = sigf(xz + rz);
            float r  = sigf(xr + rr);
            float hh = tanh_acc(xh + r * rh);
            float hn = z * hn_prev + (1.0f - z) * hh;
            hn_prev = hn;
            float* hout = (t & 1) ? h0buf : h1buf;
            __stcg(hout + (b0 + eb) * 512 + u0 + eu, hn);
            __syncwarp();
            if (lane == 0) {
                asm volatile("red.release.gpu.global.add.u32 [%0], %1;"
                             :: "l"(myctr), "r"(1u) : "memory");
            }
            outp[(size_t)t * 512] = hn;
        }
    }
}

// ============================================================================
extern "C" void kernel_launch(void* const* d_in, const int* in_sizes, int n_in,
                              void* d_out, int out_size) {
    const float* x    = (const float*)d_in[0];
    const float* W    = (const float*)d_in[1];
    const float* R    = (const float*)d_in[2];
    const float* bias = (const float*)d_in[3];
    float* out = (float*)d_out;

    float *xw_ptr, *h0_ptr, *h1_ptr;
    uint32_t *xh_ptr, *xl_ptr, *wh_ptr, *wl_ptr;
    unsigned* ctr_ptr;
    cudaGetSymbolAddress((void**)&xw_ptr, g_xw);
    cudaGetSymbolAddress((void**)&xh_ptr, g_xh);
    cudaGetSymbolAddress((void**)&xl_ptr, g_xl);
    cudaGetSymbolAddress((void**)&wh_ptr, g_wh);
    cudaGetSymbolAddress((void**)&wl_ptr, g_wl);
    cudaGetSymbolAddress((void**)&h0_ptr, g_h0);
    cudaGetSymbolAddress((void**)&h1_ptr, g_h1);
    cudaGetSymbolAddress((void**)&ctr_ptr, g_ctr);

    cudaMemsetAsync(h0_ptr, 0, 64 * 512 * sizeof(float));
    cudaMemsetAsync(ctr_ptr, 0, 8 * 32 * sizeof(unsigned));

    // ---- phase 1: convert + bf16x3 tensor GEMM (ldmatrix fragments) ----
    conv_x_kernel<<<65536, 256>>>(x, xh_ptr, xl_ptr);
    conv_w_kernel<<<1536, 256>>>(W, wh_ptr, wl_ptr);

    const int smw_bytes = 2 * 2 * 2 * 128 * APAD * 4;   // 81920
    cudaFuncSetAttribute(gemm_xw_bf16x3,
                         cudaFuncAttributeMaxDynamicSharedMemorySize, smw_bytes);
    dim3 g1(12, 512);
    gemm_xw_bf16x3<<<g1, 512, smw_bytes>>>(xh_ptr, xl_ptr, wh_ptr, wl_ptr,
                                           bias, xw_ptr);

    // ---- phase 2: v7 tensor recurrence ----
    cudaFuncSetAttribute(gru_seq_v7,
                         cudaFuncAttributeMaxDynamicSharedMemorySize, V7_BYTES);
    gru_seq_v7<<<V7_NB, 256, V7_BYTES>>>(xw_ptr, R, bias, out,
                                         h0_ptr, h1_ptr, ctr_ptr);
}

// round 17
// speedup vs baseline: 1.0398x; 1.0265x over previous
#include <cuda_runtime.h>
#include <cuda_bf16.h>
#include <cstdint>

typedef unsigned long long ull;

// ---------------- scratch (device globals: allocation-free) ----------------
__device__ float    g_xw[(size_t)64 * 1024 * 1536];   // 402 MB xw projections
__device__ uint32_t g_xh[(size_t)64 * 1024 * 256];    // x hi (bf16x2 pairs)
__device__ uint32_t g_xl[(size_t)64 * 1024 * 256];    // x lo
__device__ uint32_t g_wh[1536 * 256];                 // W^T hi
__device__ uint32_t g_wl[1536 * 256];                 // W^T lo
__device__ float    g_h0[64 * 512];
__device__ float    g_h1[64 * 512];
__device__ unsigned g_ctr[8 * 32];

// ---------------- helpers ----------------
__device__ __forceinline__ float sigf(float x) {
    return __fdividef(1.0f, 1.0f + __expf(-x));
}
__device__ __forceinline__ float tanh_acc(float x) {
    float ax = fabsf(x);
    float e = __expf(-2.0f * ax);
    float r = __fdividef(1.0f - e, 1.0f + e);
    return copysignf(r, x);
}
__device__ __forceinline__ uint32_t bf16pair(float even, float odd) {
    __nv_bfloat16 h0 = __float2bfloat16(even);
    __nv_bfloat16 h1 = __float2bfloat16(odd);
    return ((uint32_t)__bfloat16_as_ushort(h1) << 16) |
           (uint32_t)__bfloat16_as_ushort(h0);
}
__device__ __forceinline__ void split2(float x, float y,
                                       uint32_t& hi, uint32_t& lo) {
    __nv_bfloat16 hx = __float2bfloat16(x);
    __nv_bfloat16 hy = __float2bfloat16(y);
    hi = ((uint32_t)__bfloat16_as_ushort(hy) << 16) |
         (uint32_t)__bfloat16_as_ushort(hx);
    lo = bf16pair(x - __bfloat162float(hx), y - __bfloat162float(hy));
}

// ============================================================================
// Converters (phase 1 inputs)
// ============================================================================
__global__ void conv_x_kernel(const float* __restrict__ x,
                              uint32_t* __restrict__ xh,
                              uint32_t* __restrict__ xl) {
    size_t p = (size_t)blockIdx.x * 256 + threadIdx.x;
    float2 v = ((const float2*)x)[p];
    uint32_t hi, lo;
    split2(v.x, v.y, hi, lo);
    xh[p] = hi;
    xl[p] = lo;
}

__global__ void conv_w_kernel(const float* __restrict__ W,
                              uint32_t* __restrict__ wh,
                              uint32_t* __restrict__ wl) {
    int idx = blockIdx.x * 256 + threadIdx.x;
    int n = idx >> 8;
    int kp = idx & 255;
    float v0 = W[(size_t)(2 * kp) * 1536 + n];
    float v1 = W[(size_t)(2 * kp + 1) * 1536 + n];
    uint32_t hi, lo;
    split2(v0, v1, hi, lo);
    wh[idx] = hi;
    wl[idx] = lo;
}

// ============================================================================
// Phase 1 v4: xw = x @ W + b_in, bf16x3 tensor mma.
//   R11 shape (256 threads, 2 CTA/SM, 8 warps x 32M x 64N, 128x128 tile)
//   + ldmatrix fragment loads (A: m8n8.x4, B: m8n8.x2 streamed in nf loop).
// ============================================================================
#define APAD 20
#define KPT 16

__device__ __forceinline__ void cpa16(uint32_t saddr, const void* g) {
    asm volatile("cp.async.cg.shared.global [%0], [%1], 16;"
                 :: "r"(saddr), "l"(g));
}
__device__ __forceinline__ void mma_bf16(float* c, const uint32_t* a,
                                         uint32_t b0, uint32_t b1) {
    asm volatile(
        "mma.sync.aligned.m16n8k16.row.col.f32.bf16.bf16.f32 "
        "{%0,%1,%2,%3}, {%4,%5,%6,%7}, {%8,%9}, {%0,%1,%2,%3};"
        : "+f"(c[0]), "+f"(c[1]), "+f"(c[2]), "+f"(c[3])
        : "r"(a[0]), "r"(a[1]), "r"(a[2]), "r"(a[3]), "r"(b0), "r"(b1));
}
__device__ __forceinline__ void ldsm4(uint32_t* r, uint32_t addr) {
    asm volatile(
        "ldmatrix.sync.aligned.m8n8.x4.shared.b16 {%0,%1,%2,%3}, [%4];"
        : "=r"(r[0]), "=r"(r[1]), "=r"(r[2]), "=r"(r[3]) : "r"(addr));
}
__device__ __forceinline__ void ldsm2(uint32_t& r0, uint32_t& r1, uint32_t addr) {
    asm volatile(
        "ldmatrix.sync.aligned.m8n8.x2.shared.b16 {%0,%1}, [%2];"
        : "=r"(r0), "=r"(r1) : "r"(addr));
}

__global__ void __launch_bounds__(256, 2) gemm_xw_bf16x3(
    const uint32_t* __restrict__ Ahg,   // [65536][256] pairs
    const uint32_t* __restrict__ Alg,
    const uint32_t* __restrict__ Bhg,   // [1536][256] pairs (W^T)
    const uint32_t* __restrict__ Blg,
    const float* __restrict__ bias,     // [2,1536], row 0
    float* __restrict__ C)              // [65536][1536]
{
    extern __shared__ uint32_t smw[];
    uint32_t* As = smw;                         // [buf][comp][128][APAD]
    uint32_t* Bs = smw + 2 * 2 * 128 * APAD;

    const int tid = threadIdx.x;
    const int lane = tid & 31;
    const int wid = tid >> 5;                   // 0..7
    const int wm = (wid & 3) * 32;
    const int wn = (wid >> 2) * 64;
    const int bm = blockIdx.y * 128;
    const int bn = blockIdx.x * 128;

    const uint32_t as_b = (uint32_t)__cvta_generic_to_shared(As);
    const uint32_t bs_b = (uint32_t)__cvta_generic_to_shared(Bs);

    // ldmatrix per-lane addresses (bytes within a comp plane)
    // A x4 (per mf,s): rows wm+mf*16+(lane&15), col (lane>>4)*16 + s*32
    const uint32_t arow = (uint32_t)(wm + (lane & 15)) * (APAD * 4)
                        + (uint32_t)(lane >> 4) * 16;
    // B x2 (per nf,s,comp): rows wn+nf*8+(lane&7), col ((lane>>3)&1)*16 + s*32
    const uint32_t brow = (uint32_t)(wn + (lane & 7)) * (APAD * 4)
                        + (uint32_t)((lane >> 3) & 1) * 16;

    float acc[2][8][4];
#pragma unroll
    for (int mf = 0; mf < 2; mf++)
#pragma unroll
        for (int nf = 0; nf < 8; nf++)
#pragma unroll
            for (int i = 0; i < 4; i++) acc[mf][nf][i] = 0.0f;

    const int row0 = tid >> 2, j0 = (tid & 3);
    const int row1 = (tid + 256) >> 2, j1 = ((tid + 256) & 3);

    auto load_tile = [&](int kt, int buf) {
        int kw = kt * KPT;
#pragma unroll
        for (int h = 0; h < 2; h++) {
            int row = h ? row1 : row0;
            int j = h ? j1 : j0;
            uint32_t ad = as_b + ((((buf * 2 + 0) * 128 + row) * APAD + j * 4) << 2);
            cpa16(ad, Ahg + (size_t)(bm + row) * 256 + kw + j * 4);
            ad = as_b + ((((buf * 2 + 1) * 128 + row) * APAD + j * 4) << 2);
            cpa16(ad, Alg + (size_t)(bm + row) * 256 + kw + j * 4);
            uint32_t bd = bs_b + ((((buf * 2 + 0) * 128 + row) * APAD + j * 4) << 2);
            cpa16(bd, Bhg + (size_t)(bn + row) * 256 + kw + j * 4);
            bd = bs_b + ((((buf * 2 + 1) * 128 + row) * APAD + j * 4) << 2);
            cpa16(bd, Blg + (size_t)(bn + row) * 256 + kw + j * 4);
        }
    };

    load_tile(0, 0);
    asm volatile("cp.async.commit_group;");

    for (int kt = 0; kt < 16; kt++) {
        __syncthreads();
        if (kt < 15) load_tile(kt + 1, (kt + 1) & 1);
        asm volatile("cp.async.commit_group;");
        asm volatile("cp.async.wait_group 1;");
        __syncthreads();

        const int buf = kt & 1;
        const uint32_t off0 = (uint32_t)((buf * 2 + 0) * 128 * APAD) * 4;
        const uint32_t off1 = (uint32_t)((buf * 2 + 1) * 128 * APAD) * 4;

#pragma unroll
        for (int s = 0; s < 2; s++) {
            // ---- A fragments: one x4 per (mf, comp) for this s ----
            uint32_t AH[2][4], AL[2][4];
#pragma unroll
            for (int mf = 0; mf < 2; mf++) {
                uint32_t aa = as_b + arow + (uint32_t)(mf * 16) * (APAD * 4)
                            + (uint32_t)(s * 32);
                ldsm4(AH[mf], aa + off0);
                ldsm4(AL[mf], aa + off1);
            }
#pragma unroll
            for (int nf = 0; nf < 8; nf++) {
                uint32_t ba = bs_b + brow + (uint32_t)(nf * 8) * (APAD * 4)
                            + (uint32_t)(s * 32);
                uint32_t bh0, bh1, bl0, bl1;
                ldsm2(bh0, bh1, ba + off0);
                ldsm2(bl0, bl1, ba + off1);
#pragma unroll
                for (int mf = 0; mf < 2; mf++) {
                    mma_bf16(acc[mf][nf], AH[mf], bh0, bh1);   // hi*hi
                    mma_bf16(acc[mf][nf], AL[mf], bh0, bh1);   // lo*hi
                    mma_bf16(acc[mf][nf], AH[mf], bl0, bl1);   // hi*lo
                }
            }
        }
    }

    // epilogue: + bias, store
#pragma unroll
    for (int nf = 0; nf < 8; nf++) {
        int n = bn + wn + nf * 8 + 2 * (lane & 3);
        float2 bv = *(const float2*)(bias + n);
#pragma unroll
        for (int mf = 0; mf < 2; mf++) {
            int m = bm + wm + mf * 16 + (lane >> 2);
            float2 o0 = {acc[mf][nf][0] + bv.x, acc[mf][nf][1] + bv.y};
            float2 o1 = {acc[mf][nf][2] + bv.x, acc[mf][nf][3] + bv.y};
            *(float2*)(C + (size_t)m * 1536 + n) = o0;
            *(float2*)(C + (size_t)(m + 8) * 1536 + n) = o1;
        }
    }
}

// ============================================================================
// Phase 2 v7 (best): 256 CTAs = 8 bg x 32 ug, 2/SM. A = R^T, B = h.
//   Warp-local staging + per-gate-warp early release (counter = 128*t).
// ============================================================================
#define V7_NB 256
// dynamic smem layout (uint32 words)
#define V7_RLO 0        // 12288
#define V7_HHI 12288    // 2080  (8 x 260)
#define V7_HLO 14368    // 2080
#define V7_RED 16448    // 3200 floats (128 x 25)
#define V7_SB  19648    // 48
#define V7_U32 19696
#define V7_BYTES (V7_U32 * 4)

__global__ void __launch_bounds__(256, 2) gru_seq_v7(
    const float* __restrict__ xw,    // [65536, 1536]
    const float* __restrict__ rk,    // [512, 1536]
    const float* __restrict__ bias,  // [2, 1536] (row 1 = b_rec)
    float* __restrict__ out,         // [64, 1024, 512]
    float* __restrict__ h0buf,
    float* __restrict__ h1buf,
    unsigned* __restrict__ ctr)
{
    extern __shared__ uint32_t smv[];
    uint32_t* Rlo = smv + V7_RLO;
    uint32_t* hhi = smv + V7_HHI;
    uint32_t* hlo = smv + V7_HLO;
    float*    red = (float*)(smv + V7_RED);
    float*    sb  = (float*)(smv + V7_SB);

    const int tid = threadIdx.x;
    const int bgid = blockIdx.x >> 5;    // 0..7
    const int ugid = blockIdx.x & 31;    // 0..31
    const int u0 = ugid * 16;
    const int b0 = bgid * 8;

    const int w = tid >> 5;              // warp: k-chunk [64w, 64w+64)
    const int lane = tid & 31;

    // ---- preload R^T A-fragments: hi to 48 regs, lo to smem ----
    uint32_t Ah[48];
#pragma unroll
    for (int kt = 0; kt < 4; kt++)
#pragma unroll
        for (int g = 0; g < 3; g++) {
            int pb = (w * 4 + kt) * 8 + (lane & 3);
            int urow = u0 + (lane >> 2);
#pragma unroll
            for (int rr = 0; rr < 4; rr++) {
                int un = urow + ((rr & 1) ? 8 : 0);
                int kp = pb + ((rr & 2) ? 4 : 0);
                const float* q = rk + (size_t)(2 * kp) * 1536 + g * 512 + un;
                float v0 = q[0], v1 = q[1536];
                uint32_t hi, lo;
                split2(v0, v1, hi, lo);
                Ah[(kt * 3 + g) * 4 + rr] = hi;
                Rlo[((((w * 4 + kt) * 3 + g) * 4 + rr)) * 32 + lane] = lo;
            }
        }
    if (tid < 48) {
        int u = tid / 3, g = tid - u * 3;
        sb[u * 3 + g] = bias[1536 + g * 512 + u0 + u];
    }
    __syncthreads();

    // epilogue role (tid < 128): batch eb, unit eu
    const int eb = tid >> 4;
    const int eu = tid & 15;
    const float* xwp = xw + (size_t)(b0 + eb) * 1024 * 1536 + u0 + eu;
    float* outp = out + (size_t)(b0 + eb) * 524288 + u0 + eu;
    unsigned* myctr = ctr + bgid * 32;

    float hn_prev = 0.0f;

    for (int t = 0; t < 1024; t++) {
        // prefetch gate inputs (independent of h)
        float xz = 0.f, xr = 0.f, xh = 0.f;
        if (tid < 128) {
            const float* xr_ = xwp + (size_t)t * 1536;
            xz = __ldg(xr_);
            xr = __ldg(xr_ + 512);
            xh = __ldg(xr_ + 1024);
        }

        if (t > 0) {
            if (tid == 0) {
                unsigned target = (unsigned)(128 * t);   // 32 CTAs x 4 warps
                unsigned v;
                do {
                    asm volatile("ld.acquire.gpu.global.u32 %0, [%1];"
                                 : "=r"(v) : "l"(myctr) : "memory");
                } while (v < target);
            }
            __syncthreads();
        }

        // ---- warp-local staging: warp w stages k [64w,64w+64) for 8 b ----
        const float* hin = (t & 1) ? h1buf : h0buf;
#pragma unroll
        for (int i = 0; i < 4; i++) {
            int s = lane + i * 32;            // 0..127
            int b = s >> 4;                   // batch 0..7
            int f4 = s & 15;                  // float4 idx in warp's slice
            float4 v = __ldcg((const float4*)(hin + (size_t)(b0 + b) * 512 + w * 64) + f4);
            uint32_t h01, l01, h23, l23;
            split2(v.x, v.y, h01, l01);
            split2(v.z, v.w, h23, l23);
            int a = b * 260 + w * 32 + 2 * f4;
            hhi[a] = h01; hhi[a + 1] = h23;
            hlo[a] = l01; hlo[a + 1] = l23;
        }
        __syncwarp();

        // ---- tensor GEMM: A = R^T (units on M), B = h (batches on N) ----
        float accg[3][4];
#pragma unroll
        for (int g = 0; g < 3; g++)
#pragma unroll
            for (int i = 0; i < 4; i++) accg[g][i] = 0.0f;

#pragma unroll
        for (int kt = 0; kt < 4; kt++) {
            int pb = (w * 4 + kt) * 8 + (lane & 3);
            int bo = (lane >> 2) * 260;            // batch = lane>>2
            uint32_t b0h = hhi[bo + pb], b1h = hhi[bo + pb + 4];
            uint32_t b0l = hlo[bo + pb], b1l = hlo[bo + pb + 4];
#pragma unroll
            for (int g = 0; g < 3; g++) {
                const uint32_t* A = Ah + (kt * 3 + g) * 4;
                mma_bf16(accg[g], A, b0h, b1h);     // R_hi * h_hi
                mma_bf16(accg[g], A, b0l, b1l);     // R_hi * h_lo
                uint32_t al[4];
#pragma unroll
                for (int rr = 0; rr < 4; rr++)
                    al[rr] = Rlo[((((w * 4 + kt) * 3 + g) * 4 + rr)) * 32 + lane];
                mma_bf16(accg[g], al, b0h, b1h);    // R_lo * h_hi
            }
        }

        // ---- write partials: c -> D[unit row][batch col] ----
        {
            int row = lane >> 2;              // unit (low 8)
            int col = 2 * (lane & 3);         // batch
#pragma unroll
            for (int g = 0; g < 3; g++) {
                red[((col    ) * 16 + row    ) * 25 + w * 3 + g] = accg[g][0];
                red[((col + 1) * 16 + row    ) * 25 + w * 3 + g] = accg[g][1];
                red[((col    ) * 16 + row + 8) * 25 + w * 3 + g] = accg[g][2];
                red[((col + 1) * 16 + row + 8) * 25 + w * 3 + g] = accg[g][3];
            }
        }
        __syncthreads();   // red visible to gate warps

        // ---- gates + per-warp early release: gate warps 0-3 only ----
        if (tid < 128) {
            float rz = sb[eu * 3 + 0];
            float rr = sb[eu * 3 + 1];
            float rh = sb[eu * 3 + 2];
            const float* rb = red + (eb * 16 + eu) * 25;
#pragma unroll
            for (int s = 0; s < 8; s++) {
                rz += rb[s * 3 + 0];
                rr += rb[s * 3 + 1];
                rh += rb[s * 3 + 2];
            }
            float z  = sigf(xz + rz);
            float r  = sigf(xr + rr);
            float hh = tanh_acc(xh + r * rh);
            float hn = z * hn_prev + (1.0f - z) * hh;
            hn_prev = hn;
            float* hout = (t & 1) ? h0buf : h1buf;
            __stcg(hout + (b0 + eb) * 512 + u0 + eu, hn);
            __syncwarp();
            if (lane == 0) {
                asm volatile("red.release.gpu.global.add.u32 [%0], %1;"
                             :: "l"(myctr), "r"(1u) : "memory");
            }
            outp[(size_t)t * 512] = hn;
        }
    }
}

// ============================================================================
extern "C" void kernel_launch(void* const* d_in, const int* in_sizes, int n_in,
                              void* d_out, int out_size) {
    const float* x    = (const float*)d_in[0];
    const float* W    = (const float*)d_in[1];
    const float* R    = (const float*)d_in[2];
    const float* bias = (const float*)d_in[3];
    float* out = (float*)d_out;

    float *xw_ptr, *h0_ptr, *h1_ptr;
    uint32_t *xh_ptr, *xl_ptr, *wh_ptr, *wl_ptr;
    unsigned* ctr_ptr;
    cudaGetSymbolAddress((void**)&xw_ptr, g_xw);
    cudaGetSymbolAddress((void**)&xh_ptr, g_xh);
    cudaGetSymbolAddress((void**)&xl_ptr, g_xl);
    cudaGetSymbolAddress((void**)&wh_ptr, g_wh);
    cudaGetSymbolAddress((void**)&wl_ptr, g_wl);
    cudaGetSymbolAddress((void**)&h0_ptr, g_h0);
    cudaGetSymbolAddress((void**)&h1_ptr, g_h1);
    cudaGetSymbolAddress((void**)&ctr_ptr, g_ctr);

    cudaMemsetAsync(h0_ptr, 0, 64 * 512 * sizeof(float));
    cudaMemsetAsync(ctr_ptr, 0, 8 * 32 * sizeof(unsigned));

    // ---- phase 1: convert + bf16x3 tensor GEMM (256t, 2/SM, ldmatrix) ----
    conv_x_kernel<<<65536, 256>>>(x, xh_ptr, xl_ptr);
    conv_w_kernel<<<1536, 256>>>(W, wh_ptr, wl_ptr);

    const int smw_bytes = 2 * 2 * 2 * 128 * APAD * 4;   // 81920
    cudaFuncSetAttribute(gemm_xw_bf16x3,
                         cudaFuncAttributeMaxDynamicSharedMemorySize, smw_bytes);
    dim3 g1(12, 512);
    gemm_xw_bf16x3<<<g1, 256, smw_bytes>>>(xh_ptr, xl_ptr, wh_ptr, wl_ptr,
                                           bias, xw_ptr);

    // ---- phase 2: v7 tensor recurrence ----
    cudaFuncSetAttribute(gru_seq_v7,
                         cudaFuncAttributeMaxDynamicSharedMemorySize, V7_BYTES);
    gru_seq_v7<<<V7_NB, 256, V7_BYTES>>>(xw_ptr, R, bias, out,
                                         h0_ptr, h1_ptr, ctr_ptr);
}